// round 8
// baseline (speedup 1.0000x reference)
#include <cuda_runtime.h>
#include <cstdint>

#define N_NODES 100000
#define N_EDGES 1600000
#define IN_DIM 32
#define OUT_DIM 64
#define N_REL 8
#define K_DIM 256
#define K_TOT 288
#define N_KSTEP 36
#define EPS 1e-10f

static constexpr int NROWTILES = N_NODES / 16;   // 6250 exact

// Scratch (alloc-free rule): row-major — edge writes stay 128B-contiguous.
__device__ float g_num[(size_t)N_NODES * K_DIM];
__device__ float g_den[(size_t)N_NODES * N_REL];

__device__ __forceinline__ float to_tf32(float v) {
    uint32_t r;
    asm("cvt.rna.tf32.f32 %0, %1;" : "=r"(r) : "f"(v));
    return __uint_as_float(r);
}

// ---------------------------------------------------------------------------
// Kernel 1: edge scatter, 8 lanes per edge (unchanged — R6 best).
// ---------------------------------------------------------------------------
__global__ void scatter_kernel(const int* __restrict__ edge_list,
                               const float* __restrict__ edge_weight,
                               const float* __restrict__ x) {
    const int tid   = threadIdx.x;
    const int gwarp = (blockIdx.x * blockDim.x + tid) >> 5;
    const int lane  = tid & 31;
    const int sub   = lane >> 3;
    const int i8    = lane & 7;

    const int e0 = gwarp * 4;

    int   ev = 0;
    float wv = 0.f;
    if (lane < 12)      ev = edge_list[(size_t)e0 * 3 + lane];
    else if (lane < 16) wv = edge_weight[e0 + (lane - 12)];

    const int   src = __shfl_sync(0xffffffffu, ev, sub * 3 + 0);
    const int   dst = __shfl_sync(0xffffffffu, ev, sub * 3 + 1);
    const int   rel = __shfl_sync(0xffffffffu, ev, sub * 3 + 2);
    const float w   = __shfl_sync(0xffffffffu, wv, 12 + sub);

    const float4 v =
        reinterpret_cast<const float4*>(x + (size_t)src * IN_DIM)[i8];
    float* basep = g_num + (size_t)dst * K_DIM + rel * IN_DIM + i8 * 4;

    asm volatile(
        "red.global.add.v4.f32 [%0], {%1, %2, %3, %4};"
        :: "l"(basep),
           "f"(v.x * w), "f"(v.y * w), "f"(v.z * w), "f"(v.w * w)
        : "memory");

    if (i8 == 0)
        atomicAdd(g_den + (size_t)dst * N_REL + rel, w);
}

// ---------------------------------------------------------------------------
// Kernel 2: tf32 MMA GEMM.
//   - normalization + tf32 rounding done at staging (producer side)
//   - k-slot permutation so A fragments are LDS.64 (pairs adjacent)
//   - per-warp double-buffered staging, stride-40 rows (conflict-free)
// ---------------------------------------------------------------------------
#define BF_FLOAT2 (N_KSTEP * 8 * 32)
#define BF_BYTES  (BF_FLOAT2 * 8)               // 73728
#define WROW 40                                  // floats per staged row
#define WBUF_FLOATS (16 * WROW)                  // 640 per buffer
#define WARP_SMEM_FLOATS (128 + 2 * WBUF_FLOATS) // dinvT + 2 buffers = 1408
#define WBUF_OFF  (BF_BYTES + OUT_DIM * 4)       // 73984
#define SMEM_TOTAL (WBUF_OFF + 16 * WARP_SMEM_FLOATS * 4)  // 164096

__device__ __forceinline__ void mma_tf32(float c[4], uint32_t a0, uint32_t a1,
                                         uint32_t a2, uint32_t a3,
                                         uint32_t b0, uint32_t b1) {
    asm volatile(
        "mma.sync.aligned.m16n8k8.row.col.f32.tf32.tf32.f32 "
        "{%0,%1,%2,%3}, {%4,%5,%6,%7}, {%8,%9}, {%0,%1,%2,%3};"
        : "+f"(c[0]), "+f"(c[1]), "+f"(c[2]), "+f"(c[3])
        : "r"(a0), "r"(a1), "r"(a2), "r"(a3), "r"(b0), "r"(b1));
}

__global__ __launch_bounds__(512, 1)
void gemm_mma_kernel(const float* __restrict__ x,
                     const float* __restrict__ Wl,
                     const float* __restrict__ bl,
                     const float* __restrict__ Ws,
                     const float* __restrict__ bs,
                     float* __restrict__ out) {
    extern __shared__ char smem[];
    float2* sBf   = reinterpret_cast<float2*>(smem);
    float*  sBias = reinterpret_cast<float*>(smem + BF_BYTES);

    const int tid  = threadIdx.x;
    const int wid  = tid >> 5;
    const int lane = tid & 31;
    const int g    = lane >> 2;
    const int tig  = lane & 3;

    float* wdinv = reinterpret_cast<float*>(smem + WBUF_OFF) +
                   wid * WARP_SMEM_FLOATS;               // [16 rows][8 kb]
    float* wbuf0 = wdinv + 128;
    float* wbuf1 = wbuf0 + WBUF_FLOATS;

    const int ldrow = lane >> 3;          // staging row subgroup 0..3
    const int ldcol = (lane & 7) * 4;     // float offset in 32-float chunk

    // ---- stage B fragments once (k-slot permuted: slot tt <-> k = s*8+2*tt) ----
    for (int idx = tid; idx < BF_FLOAT2; idx += 512) {
        const int l  = idx & 31;
        const int j  = (idx >> 5) & 7;
        const int s  = idx >> 8;
        const int gg = l >> 2, tt = l & 3;
        const int n  = j * 8 + gg;
        const int k0 = s * 8 + 2 * tt;
        const int k1 = k0 + 1;
        const float v0 = (k0 < K_DIM) ? Wl[(size_t)k0 * OUT_DIM + n]
                                      : Ws[(size_t)(k0 - K_DIM) * OUT_DIM + n];
        const float v1 = (k1 < K_DIM) ? Wl[(size_t)k1 * OUT_DIM + n]
                                      : Ws[(size_t)(k1 - K_DIM) * OUT_DIM + n];
        sBf[idx] = make_float2(to_tf32(v0), to_tf32(v1));
    }
    if (tid < OUT_DIM) sBias[tid] = bl[tid] + bs[tid];
    __syncthreads();

    const int nwarps = gridDim.x * 16;

    for (int t = blockIdx.x * 16 + wid; t < NROWTILES; t += nwarps) {
        // ---- per-warp dinv table: wdinv[i] = 1/(g_den[t*128+i]+eps) ----
        {
            const float4 dv = reinterpret_cast<const float4*>(
                g_den + (size_t)t * 128)[lane];
            float4 r;
            r.x = __fdividef(1.f, dv.x + EPS);
            r.y = __fdividef(1.f, dv.y + EPS);
            r.z = __fdividef(1.f, dv.z + EPS);
            r.w = __fdividef(1.f, dv.w + EPS);
            *reinterpret_cast<float4*>(wdinv + lane * 4) = r;
        }
        __syncwarp();

        float acc[8][4];
#pragma unroll
        for (int j = 0; j < 8; j++)
#pragma unroll
            for (int c = 0; c < 4; c++) acc[j][c] = 0.f;

        const float* srcA = g_num + (size_t)t * 16 * K_DIM;
        const float* srcX = x + (size_t)t * 16 * IN_DIM;

        // prefetch kblock 0
        float4 pf[4];
#pragma unroll
        for (int i = 0; i < 4; i++)
            pf[i] = *reinterpret_cast<const float4*>(
                srcA + (size_t)(i * 4 + ldrow) * K_DIM + ldcol);

#pragma unroll
        for (int kb = 0; kb < 9; kb++) {
            float* buf = (kb & 1) ? wbuf1 : wbuf0;

            // ---- stage current block: normalize + tf32 + STS.128 ----
#pragma unroll
            for (int i = 0; i < 4; i++) {
                const int r = i * 4 + ldrow;
                const float dvv = (kb < 8) ? wdinv[r * 8 + kb] : 1.f;
                float4 v = pf[i];
                v.x = to_tf32(v.x * dvv); v.y = to_tf32(v.y * dvv);
                v.z = to_tf32(v.z * dvv); v.w = to_tf32(v.w * dvv);
                *reinterpret_cast<float4*>(buf + r * WROW + ldcol) = v;
            }

            // ---- prefetch next block (in flight during MMA) ----
            if (kb < 7) {
#pragma unroll
                for (int i = 0; i < 4; i++)
                    pf[i] = *reinterpret_cast<const float4*>(
                        srcA + (size_t)(i * 4 + ldrow) * K_DIM + (kb + 1) * 32 + ldcol);
            } else if (kb == 7) {
#pragma unroll
                for (int i = 0; i < 4; i++)
                    pf[i] = *reinterpret_cast<const float4*>(
                        srcX + (size_t)(i * 4 + ldrow) * IN_DIM + ldcol);
            }
            __syncwarp();

            // ---- MMA: pure LDS.64 + HMMA ----
#pragma unroll
            for (int ss = 0; ss < 4; ss++) {
                const int fo = ss * 8 + 2 * tig;
                const float2 pA0 = *reinterpret_cast<const float2*>(
                    buf + g * WROW + fo);
                const float2 pA1 = *reinterpret_cast<const float2*>(
                    buf + (g + 8) * WROW + fo);
                const uint32_t a0 = __float_as_uint(pA0.x);
                const uint32_t a2 = __float_as_uint(pA0.y);
                const uint32_t a1 = __float_as_uint(pA1.x);
                const uint32_t a3 = __float_as_uint(pA1.y);
                const float2* bf = sBf + (kb * 4 + ss) * 256 + lane;
#pragma unroll
                for (int j = 0; j < 8; j++) {
                    const float2 bb = bf[j * 32];
                    mma_tf32(acc[j], a0, a1, a2, a3,
                             __float_as_uint(bb.x), __float_as_uint(bb.y));
                }
            }
            __syncwarp();   // buf reusable two iterations later
        }

        // ---- epilogue: bias + relu + float2 stores ----
        const int row0 = t * 16 + g;
        const int row1 = row0 + 8;
#pragma unroll
        for (int j = 0; j < 8; j++) {
            const int col = j * 8 + tig * 2;
            const float b0 = sBias[col], b1 = sBias[col + 1];
            float2 v0 = make_float2(fmaxf(acc[j][0] + b0, 0.f),
                                    fmaxf(acc[j][1] + b1, 0.f));
            float2 v1 = make_float2(fmaxf(acc[j][2] + b0, 0.f),
                                    fmaxf(acc[j][3] + b1, 0.f));
            *reinterpret_cast<float2*>(out + (size_t)row0 * OUT_DIM + col) = v0;
            *reinterpret_cast<float2*>(out + (size_t)row1 * OUT_DIM + col) = v1;
        }
    }
}

// ---------------------------------------------------------------------------
// Launch
// ---------------------------------------------------------------------------
extern "C" void kernel_launch(void* const* d_in, const int* in_sizes, int n_in,
                              void* d_out, int out_size) {
    const float* x     = (const float*)d_in[0];
    const int*   edges = (const int*)  d_in[1];
    const float* ew    = (const float*)d_in[2];
    const float* Wl    = (const float*)d_in[3];
    const float* bl    = (const float*)d_in[4];
    const float* Ws    = (const float*)d_in[5];
    const float* bs    = (const float*)d_in[6];
    float*       out   = (float*)d_out;

    void* pnum = nullptr; void* pden = nullptr;
    cudaGetSymbolAddress(&pnum, g_num);
    cudaGetSymbolAddress(&pden, g_den);
    cudaMemsetAsync(pnum, 0, (size_t)N_NODES * K_DIM * sizeof(float), 0);
    cudaMemsetAsync(pden, 0, (size_t)N_NODES * N_REL * sizeof(float), 0);

    scatter_kernel<<<(N_EDGES * 8) / 256, 256>>>(edges, ew, x);

    cudaFuncSetAttribute(gemm_mma_kernel,
                         cudaFuncAttributeMaxDynamicSharedMemorySize,
                         SMEM_TOTAL);
    gemm_mma_kernel<<<148, 512, SMEM_TOTAL>>>(x, Wl, bl, Ws, bs, out);
}